// round 11
// baseline (speedup 1.0000x reference)
#include <cuda_runtime.h>
#include <math.h>

typedef unsigned long long ull;

#define NB      16
#define NT      256
#define TST     800
#define NL      16
// B=4, R=S=128, CC=64, CLASSES=256. CTA g owns 8 h-channels [g*8, g*8+8), 16 classes.

// ---------------- device scratch (allocation-free) ----------------
__device__ float g_queue[261120];            // dilation rings, slot = [b][128]
__device__ float g_condz[16*4*4*256];        // [l][e][b][row]  (Wcond@c + bc)
__device__ float g_condtop[4*4*128];         // [e][b][s]       (Wcond_top@c + bfc)
__device__ float g_bskip[128];               // bskip0 + sum_l bskip_l
__device__ float g_Wskip0T[128*128];         // [r][s]
__device__ float g_WskipT[16*128*128];       // [l][r][s]
__device__ float g_hxA[NB*32];               // h slices, 128B/CTA (even layers)
__device__ float g_hxB[NB*32];               // (odd layers)
__device__ float g_skipP[NB*512];            // [g][b][s] skip partials
__device__ volatile unsigned g_flag[NB*32];  // per-CTA epoch flags, 128B stride

__constant__ int c_dil[NL]  = {1,2,4,8,16,32,64,128,1,2,4,8,16,32,64,128};
__constant__ int c_qoff[NL] = {0,512,1536,3584,7680,15872,32256,65024,
                               130560,131072,132096,134144,138240,146432,162816,195584};

__device__ __forceinline__ unsigned fkey(float v) {   // monotonic float->uint
    unsigned u = __float_as_uint(v);
    return (u & 0x80000000u) ? ~u : (u | 0x80000000u);
}

// ---------------- prep kernels ----------------
__global__ void reset_flags() {
    int i = blockIdx.x * blockDim.x + threadIdx.x;
    if (i < NB*32) g_flag[i] = 0u;
}
__global__ void prep_condz(const float* __restrict__ enc, const float* __restrict__ Wcond,
                           const float* __restrict__ bc) {
    int idx = blockIdx.x * blockDim.x + threadIdx.x;   // 65536
    int row = idx & 255, b = (idx >> 8) & 3, e = (idx >> 10) & 3, l = idx >> 12;
    float v = bc[l*256 + row];
    const float* w = Wcond + (l*256 + row)*64;
    #pragma unroll 8
    for (int c = 0; c < 64; ++c) v = fmaf(w[c], enc[b*256 + c*4 + e], v);
    g_condz[((l*4 + e)*4 + b)*256 + row] = v;
}
__global__ void prep_condtop(const float* __restrict__ enc, const float* __restrict__ Wct,
                             const float* __restrict__ bfc) {
    int idx = blockIdx.x * blockDim.x + threadIdx.x;   // 2048
    int s = idx & 127, b = (idx >> 7) & 3, e = idx >> 9;
    float v = bfc[s];
    #pragma unroll 8
    for (int c = 0; c < 64; ++c) v = fmaf(Wct[s*64 + c], enc[b*256 + c*4 + e], v);
    g_condtop[(e*4 + b)*128 + s] = v;
}
__global__ void prep_bskip(const float* __restrict__ b0, const float* __restrict__ bl) {
    int s = threadIdx.x;
    float v = b0[s];
    #pragma unroll
    for (int l = 0; l < NL; ++l) v += bl[l*128 + s];
    g_bskip[s] = v;
}
__global__ void prep_t0(const float* __restrict__ Wskip0) {
    int i = blockIdx.x * blockDim.x + threadIdx.x;     // 16384
    g_Wskip0T[(i >> 7)*128 + (i & 127)] = Wskip0[(i & 127)*128 + (i >> 7)];
}
__global__ void prep_t1(const float* __restrict__ Wskip_l) {
    int i = blockIdx.x * blockDim.x + threadIdx.x;     // 262144
    int l = i >> 14, r = (i >> 7) & 127, s = i & 127;
    g_WskipT[(l*128 + r)*128 + s] = Wskip_l[(l*128 + s)*128 + r];
}

// ---------------- main persistent kernel ----------------
__global__ void __launch_bounds__(NT, 1)
wnet_main(const float* __restrict__ Wf,   const float* __restrict__ bf,
          const float* __restrict__ Wc,   const float* __restrict__ Wres,
          const float* __restrict__ bres, const float* __restrict__ Wfc,
          const float* __restrict__ Wlog, const float* __restrict__ blog,
          float* __restrict__ out)
{
    const int g   = blockIdx.x;
    const int tid = threadIdx.x;

    typedef float Row[132];
    __shared__ float s_res[4][132];   // full residual [b][k]
    __shared__ float s_h[4][132];     // full h (gathered) / relu in tail
    __shared__ float s_qA[4][132];    // q0 double buffer
    __shared__ float s_qB[4][132];
    __shared__ float s_z[16][4];
    __shared__ ull   s_keys[8][4];
    __shared__ float s_x[4], s_xp[4];

    // roles
    const int r7 = tid & 127, bb = tid >> 7;               // (r7, bb) & (r7, bb+2)
    const int dn4 = tid >> 2, t4 = tid & 3;                // z: 64 dots x 4 lanes
    const int rowA = dn4 >> 2, bA = dn4 & 3;               // rowA in [0,16)
    const int zrow = (rowA < 8) ? (g*8 + rowA) : (128 + g*8 + rowA - 8);

    if (tid < 4) { s_x[tid] = 128.0f/127.5f - 1.0f; s_xp[tid] = 0.0f; }
    // q0 for (t=0, l=0): t < d  -> zeros
    for (int i = tid; i < 512; i += NT) s_qA[i >> 7][i & 127] = 0.f;
    unsigned ep = 0;
    __syncthreads();

    Row* qcur = s_qA;
    Row* qnxt = s_qB;

    for (int t = 0; t < TST; ++t) {
        const int e = t / 200;

        // first causal conv -> full res
        for (int i = tid; i < 512; i += NT) {
            int b = i >> 7, k = i & 127;
            s_res[b][k] = fmaf(s_xp[b], Wf[2*k], fmaf(s_x[b], Wf[2*k+1], bf[k]));
        }
        __syncthreads();

        // skip init: Wskip0 over this CTA's 8 input channels
        float sa0 = 0.f, sa1 = 0.f;
        #pragma unroll
        for (int j = 0; j < 8; ++j) {
            float w = g_Wskip0T[(g*8 + j)*128 + r7];
            sa0 = fmaf(w, s_res[bb    ][g*8 + j], sa0);
            sa1 = fmaf(w, s_res[bb + 2][g*8 + j], sa1);
        }

        #pragma unroll 1
        for (int l = 0; l < NL; ++l) {
            // ---- z slice: Wc0.q0 + Wc1.res + condz ----
            {
                const float2* wp = reinterpret_cast<const float2*>(Wc) + (l*256 + zrow)*128;
                float acc = 0.f;
                #pragma unroll
                for (int i = 0; i < 32; ++i) {
                    int k = t4 + 4*i;
                    float2 w = wp[k];
                    acc = fmaf(w.x, qcur[bA][k], acc);
                    acc = fmaf(w.y, s_res[bA][k], acc);
                }
                acc += __shfl_down_sync(0xffffffffu, acc, 2);
                acc += __shfl_down_sync(0xffffffffu, acc, 1);
                if (t4 == 0)
                    s_z[rowA][bA] = acc + g_condz[((l*4 + e)*4 + bA)*256 + zrow];
            }
            __syncthreads();

            // ---- gated activation + publish own 32 h values ----
            float* hx = (l & 1) ? g_hxB : g_hxA;
            if (tid < 32) {
                int j = tid >> 2, b = tid & 3;
                float hv = tanhf(s_z[j + 8][b]) / (1.f + expf(-s_z[j][b]));
                __stcg(&hx[g*32 + tid], hv);     // layout [j][b]
                __threadfence();
            }
            __syncthreads();
            ++ep;
            if (tid == 0) g_flag[g*32] = ep;

            // ---- wait all + gather full h ----
            if (tid < 16) {
                while (g_flag[tid*32] < ep) { }
                __threadfence();
                const float4* s4 = (const float4*)(hx + tid*32);
                #pragma unroll
                for (int q = 0; q < 8; ++q) {
                    float4 v = __ldcg(s4 + q);
                    int ch = tid*8 + q;
                    s_h[0][ch] = v.x; s_h[1][ch] = v.y; s_h[2][ch] = v.z; s_h[3][ch] = v.w;
                }
            }
            __syncthreads();

            // ---- prefetch next q0 into registers (off critical path) ----
            float pf0 = 0.f, pf1 = 0.f;
            if (l < 15) {
                int dn = c_dil[l + 1];
                if (t >= dn) {
                    const float* qn = g_queue + c_qoff[l + 1] + (t & (dn - 1))*512;
                    pf0 = __ldcg(qn + tid);
                    pf1 = __ldcg(qn + 256 + tid);
                }
            } else if (t + 1 < TST) {       // layer 0 of next step (d=1, slot already final)
                const float* qn = g_queue + c_qoff[0];
                pf0 = __ldcg(qn + tid);
                pf1 = __ldcg(qn + 256 + tid);
            }

            // ---- ring push (own slice, old res) + redundant full res update ----
            {
                float old0 = s_res[bb][r7], old1 = s_res[bb + 2][r7];
                if ((r7 >> 3) == g) {
                    float* qb = g_queue + c_qoff[l] + (t & (c_dil[l] - 1))*512;
                    __stcg(qb + bb*128 + r7,       old0);
                    __stcg(qb + (bb + 2)*128 + r7, old1);
                }
                if (l < 15) {
                    const float4* wr = (const float4*)(Wres + (l*128 + r7)*128);
                    const float4* h0 = (const float4*)&s_h[bb][0];
                    const float4* h1 = (const float4*)&s_h[bb + 2][0];
                    float a0 = 0.f, a1 = 0.f;
                    #pragma unroll 8
                    for (int i = 0; i < 32; ++i) {
                        float4 w = __ldg(wr + i);
                        float4 x0 = h0[i], x1 = h1[i];
                        a0 = fmaf(w.x, x0.x, a0); a0 = fmaf(w.y, x0.y, a0);
                        a0 = fmaf(w.z, x0.z, a0); a0 = fmaf(w.w, x0.w, a0);
                        a1 = fmaf(w.x, x1.x, a1); a1 = fmaf(w.y, x1.y, a1);
                        a1 = fmaf(w.z, x1.z, a1); a1 = fmaf(w.w, x1.w, a1);
                    }
                    float bv = bres[l*128 + r7];
                    s_res[bb][r7]     = old0 + a0 + bv;    // single-owner element
                    s_res[bb + 2][r7] = old1 + a1 + bv;
                }
            }

            // ---- skip accumulate from full h (own 8 channels) ----
            #pragma unroll
            for (int j = 0; j < 8; ++j) {
                float w = g_WskipT[(l*128 + g*8 + j)*128 + r7];
                sa0 = fmaf(w, s_h[bb    ][g*8 + j], sa0);
                sa1 = fmaf(w, s_h[bb + 2][g*8 + j], sa1);
            }

            // park prefetched q0, swap buffers
            qnxt[bb][r7]     = pf0;
            qnxt[bb + 2][r7] = pf1;
            __syncthreads();
            { Row* tmp = qcur; qcur = qnxt; qnxt = tmp; }
        }

        // ---- tail: skip exchange (the only tail sync) ----
        __stcg(&g_skipP[(g*4 + bb)*128 + r7],     sa0);
        __stcg(&g_skipP[(g*4 + bb + 2)*128 + r7], sa1);
        __threadfence();
        __syncthreads();
        ++ep;
        if (tid == 0) g_flag[g*32] = ep;
        if (tid < 16) {
            while (g_flag[tid*32] < ep) { }
            __threadfence();
        }
        __syncthreads();

        // redundant relu(skip) into s_h
        {
            float v0 = g_bskip[r7], v1 = v0;
            #pragma unroll
            for (int gg = 0; gg < NB; ++gg) {
                v0 += __ldcg(&g_skipP[(gg*4 + bb)*128 + r7]);
                v1 += __ldcg(&g_skipP[(gg*4 + bb + 2)*128 + r7]);
            }
            s_h[bb][r7]     = fmaxf(v0, 0.f);
            s_h[bb + 2][r7] = fmaxf(v1, 0.f);
        }
        __syncthreads();

        // redundant fc -> relu(s) into qnxt (free buffer)
        {
            const float4* wf = (const float4*)(Wfc + r7*128);
            const float4* h0 = (const float4*)&s_h[bb][0];
            const float4* h1 = (const float4*)&s_h[bb + 2][0];
            float f0 = 0.f, f1 = 0.f;
            #pragma unroll 8
            for (int i = 0; i < 32; ++i) {
                float4 w = __ldg(wf + i);
                float4 x0 = h0[i], x1 = h1[i];
                f0 = fmaf(w.x, x0.x, f0); f0 = fmaf(w.y, x0.y, f0);
                f0 = fmaf(w.z, x0.z, f0); f0 = fmaf(w.w, x0.w, f0);
                f1 = fmaf(w.x, x1.x, f1); f1 = fmaf(w.y, x1.y, f1);
                f1 = fmaf(w.z, x1.z, f1); f1 = fmaf(w.w, x1.w, f1);
            }
            qnxt[bb][r7]     = fmaxf(f0 + g_condtop[(e*4 + bb)*128 + r7],     0.f);
            qnxt[bb + 2][r7] = fmaxf(f1 + g_condtop[(e*4 + bb + 2)*128 + r7], 0.f);
        }
        __syncthreads();

        // redundant logits (thread owns class tid, all 4 batches) + local argmax
        {
            const float4* wl = (const float4*)(Wlog + tid*128);
            float l0 = 0.f, l1 = 0.f, l2 = 0.f, l3 = 0.f;
            #pragma unroll 8
            for (int i = 0; i < 32; ++i) {
                float4 w = __ldg(wl + i);
                float4 x0 = ((const float4*)&qnxt[0][0])[i];
                float4 x1 = ((const float4*)&qnxt[1][0])[i];
                float4 x2 = ((const float4*)&qnxt[2][0])[i];
                float4 x3 = ((const float4*)&qnxt[3][0])[i];
                l0 = fmaf(w.x, x0.x, l0); l0 = fmaf(w.y, x0.y, l0); l0 = fmaf(w.z, x0.z, l0); l0 = fmaf(w.w, x0.w, l0);
                l1 = fmaf(w.x, x1.x, l1); l1 = fmaf(w.y, x1.y, l1); l1 = fmaf(w.z, x1.z, l1); l1 = fmaf(w.w, x1.w, l1);
                l2 = fmaf(w.x, x2.x, l2); l2 = fmaf(w.y, x2.y, l2); l2 = fmaf(w.z, x2.z, l2); l2 = fmaf(w.w, x2.w, l2);
                l3 = fmaf(w.x, x3.x, l3); l3 = fmaf(w.y, x3.y, l3); l3 = fmaf(w.z, x3.z, l3); l3 = fmaf(w.w, x3.w, l3);
            }
            float bl = blog[tid];
            l0 += bl; l1 += bl; l2 += bl; l3 += bl;
            if ((tid >> 4) == g) {       // CTA g owns classes [g*16, g*16+16)
                out[(0*256 + tid)*TST + t] = l0;
                out[(1*256 + tid)*TST + t] = l1;
                out[(2*256 + tid)*TST + t] = l2;
                out[(3*256 + tid)*TST + t] = l3;
            }
            // packed keys: (monotone value, 255-cls) -> max == first-occurrence argmax
            ull k0 = ((ull)fkey(l0) << 32) | (unsigned)(255 - tid);
            ull k1 = ((ull)fkey(l1) << 32) | (unsigned)(255 - tid);
            ull k2 = ((ull)fkey(l2) << 32) | (unsigned)(255 - tid);
            ull k3 = ((ull)fkey(l3) << 32) | (unsigned)(255 - tid);
            #pragma unroll
            for (int off = 16; off > 0; off >>= 1) {
                ull o0 = __shfl_down_sync(0xffffffffu, k0, off);
                ull o1 = __shfl_down_sync(0xffffffffu, k1, off);
                ull o2 = __shfl_down_sync(0xffffffffu, k2, off);
                ull o3 = __shfl_down_sync(0xffffffffu, k3, off);
                if (o0 > k0) k0 = o0;
                if (o1 > k1) k1 = o1;
                if (o2 > k2) k2 = o2;
                if (o3 > k3) k3 = o3;
            }
            if ((tid & 31) == 0) {
                int w = tid >> 5;
                s_keys[w][0] = k0; s_keys[w][1] = k1; s_keys[w][2] = k2; s_keys[w][3] = k3;
            }
        }
        __syncthreads();
        if (tid < 4) {
            ull best = s_keys[0][tid];
            #pragma unroll
            for (int w = 1; w < 8; ++w) if (s_keys[w][tid] > best) best = s_keys[w][tid];
            int cls = 255 - (int)(best & 0xffu);
            s_xp[tid] = s_x[tid];
            s_x[tid]  = (float)cls / 127.5f - 1.0f;
        }
        __syncthreads();
    }
}

// ---------------- launch ----------------
extern "C" void kernel_launch(void* const* d_in, const int* in_sizes, int n_in,
                              void* d_out, int out_size) {
    const float* enc       = (const float*)d_in[0];
    const float* Wf        = (const float*)d_in[1];
    const float* bf        = (const float*)d_in[2];
    const float* Wc        = (const float*)d_in[3];
    const float* bc        = (const float*)d_in[4];
    const float* Wcond     = (const float*)d_in[5];
    const float* Wres      = (const float*)d_in[6];
    const float* bres      = (const float*)d_in[7];
    const float* Wskip_l   = (const float*)d_in[8];
    const float* bskip_l   = (const float*)d_in[9];
    const float* Wskip0    = (const float*)d_in[10];
    const float* bskip0    = (const float*)d_in[11];
    const float* Wcond_top = (const float*)d_in[12];
    const float* Wfc       = (const float*)d_in[13];
    const float* bfc       = (const float*)d_in[14];
    const float* Wlog      = (const float*)d_in[15];
    const float* blog      = (const float*)d_in[16];
    float* out = (float*)d_out;

    reset_flags <<<2,   256>>>();
    prep_condz  <<<256, 256>>>(enc, Wcond, bc);
    prep_condtop<<<8,   256>>>(enc, Wcond_top, bfc);
    prep_bskip  <<<1,   128>>>(bskip0, bskip_l);
    prep_t0     <<<64,  256>>>(Wskip0);
    prep_t1     <<<1024,256>>>(Wskip_l);
    wnet_main   <<<NB,  NT >>>(Wf, bf, Wc, Wres, bres, Wfc, Wlog, blog, out);
}

// round 16
// speedup vs baseline: 1.9595x; 1.9595x over previous
#include <cuda_runtime.h>
#include <math.h>

typedef unsigned long long ull;

#define NT   512
#define TST  800
#define NL   16
// B=4 (one CTA per batch element), R=S=128, CC=64, CLASSES=256

// ---------------- device scratch (allocation-free) ----------------
__device__ float g_ring[4*65280];      // per-batch dilation rings [b][sum(dil)*128]
__device__ float g_condz[4*NL*4*256];  // [b][l][e][row]: Wcond@c + bc (folded per launch)

__constant__ int c_dil[NL]  = {1,2,4,8,16,32,64,128,1,2,4,8,16,32,64,128};
// cumulative ring offsets (128-float slots per dilation step); end = 65280 = 510*128
__constant__ int c_roff[NL] = {0,128,384,896,1920,3968,8064,16256,
                               32640,32768,33024,33536,34560,36608,40704,48896};

// ---------------- packed f32x2 helpers (bit-exact fp32 rounding) ----------------
__device__ __forceinline__ ull pk2(float lo, float hi) {
    ull r; asm("mov.b64 %0, {%1, %2};" : "=l"(r) : "f"(lo), "f"(hi)); return r;
}
__device__ __forceinline__ ull fma2(ull a, ull b, ull c) {
    ull d; asm("fma.rn.f32x2 %0, %1, %2, %3;" : "=l"(d) : "l"(a), "l"(b), "l"(c)); return d;
}
__device__ __forceinline__ float unp_sum(ull v) {
    float lo, hi; asm("mov.b64 {%0, %1}, %2;" : "=f"(lo), "=f"(hi) : "l"(v));
    return lo + hi;
}
__device__ __forceinline__ unsigned fkey(float v) {   // monotonic float -> uint
    unsigned u = __float_as_uint(v);
    return (u & 0x80000000u) ? ~u : (u | 0x80000000u);
}

// 128-wide row dot, 8 lanes/row, row-contiguous weights, x given as packed pairs.
// Full sum valid on ln8==0.
__device__ __forceinline__ float dot128(const float* __restrict__ wrow,
                                        const ull* __restrict__ xu, int ln8) {
    ull acc = pk2(0.f, 0.f);
    const float4* w4 = (const float4*)wrow + ln8;
    #pragma unroll
    for (int i = 0; i < 4; ++i) {
        float4 wv = __ldg(w4 + (i << 3));
        int n = ln8 + (i << 3);                 // float4 index -> float pairs 2n, 2n+1
        acc = fma2(pk2(wv.x, wv.y), xu[2*n],     acc);
        acc = fma2(pk2(wv.z, wv.w), xu[2*n + 1], acc);
    }
    float a = unp_sum(acc);
    a += __shfl_down_sync(0xffffffffu, a, 4);
    a += __shfl_down_sync(0xffffffffu, a, 2);
    a += __shfl_down_sync(0xffffffffu, a, 1);
    return a;
}

// ---------------- the single kernel ----------------
__global__ void __launch_bounds__(NT, 1)
wnet4(const float* __restrict__ enc,  const float* __restrict__ Wf,
      const float* __restrict__ bf,   const float* __restrict__ Wc,
      const float* __restrict__ bc,   const float* __restrict__ Wcond,
      const float* __restrict__ Wres, const float* __restrict__ bres,
      const float* __restrict__ Wskip,const float* __restrict__ bskipl,
      const float* __restrict__ Wskip0,const float* __restrict__ bskip0,
      const float* __restrict__ Wct,  const float* __restrict__ Wfc,
      const float* __restrict__ bfc,  const float* __restrict__ Wlog,
      const float* __restrict__ blog, float* __restrict__ out)
{
    __shared__ __align__(16) float2 s_qr[128];     // (q0[k], res[k]) pairs
    __shared__ __align__(16) float  s_ct[4*128];   // condtop[e][s] (+bfc)
    __shared__ __align__(16) float  s_bsk[128];    // bskip0 + sum_l bskip_l
    __shared__ __align__(16) float  s_z[256];      // z rows / logits (reused)
    __shared__ __align__(16) float  s_h[128];
    __shared__ __align__(16) float  s_res[128];
    __shared__ __align__(16) float  s_skip[128];
    __shared__ __align__(16) float  s_rl[128];
    __shared__ __align__(16) float  s_s2[128];
    __shared__ float s_xv[2];                      // x, xp

    const int b    = blockIdx.x;
    const int tid  = threadIdx.x;
    const int grp8 = tid >> 3, ln8 = tid & 7;      // 64 row-groups x 8 lanes
    float* ring  = g_ring + b*65280;
    float* condz = g_condz + b*(NL*4*256);
    const ull* hu  = (const ull*)s_h;
    const ull* rlu = (const ull*)s_rl;
    const ull* s2u = (const ull*)s_s2;
    const ull* qru = (const ull*)s_qr;

    // ---- prologue: fold conditioning for this batch element ----
    for (int j = tid; j < NL*4*256; j += NT) {     // condz[l][e][row]
        int r = j & 255, e = (j >> 8) & 3, l = j >> 10;
        float v = bc[l*256 + r];
        const float* w  = Wcond + (l*256 + r)*64;
        const float* eb = enc + b*256 + e;         // enc[b][c][e], stride 4 over c
        #pragma unroll 8
        for (int c = 0; c < 64; ++c) v = fmaf(w[c], eb[c*4], v);
        condz[(l*4 + e)*256 + r] = v;
    }
    for (int j = tid; j < 4*128; j += NT) {        // condtop[e][s]
        int s = j & 127, e = j >> 7;
        float v = bfc[s];
        const float* w  = Wct + s*64;
        const float* eb = enc + b*256 + e;
        #pragma unroll 8
        for (int c = 0; c < 64; ++c) v = fmaf(w[c], eb[c*4], v);
        s_ct[e*128 + s] = v;
    }
    for (int s = tid; s < 128; s += NT) {
        float v = bskip0[s];
        #pragma unroll
        for (int l = 0; l < NL; ++l) v += bskipl[l*128 + s];
        s_bsk[s] = v;
    }
    if (tid == 0) { s_xv[0] = 128.0f/127.5f - 1.0f; s_xv[1] = 0.0f; }
    __syncthreads();

    for (int t = 0; t < TST; ++t) {
        const int e = t / 200;

        // ---- first causal conv: res = xp*W0 + x*W1 + b ----
        {
            float x = s_xv[0], xp = s_xv[1];
            for (int k = tid; k < 128; k += NT)
                s_res[k] = fmaf(xp, __ldg(Wf + 2*k), fmaf(x, __ldg(Wf + 2*k + 1), __ldg(bf + k)));
        }
        __syncthreads();

        // ---- skip init: skip[s] = Wskip0[s,:] . res ----
        {
            const ull* ru = (const ull*)s_res;
            #pragma unroll
            for (int p = 0; p < 2; ++p) {
                int s = (p << 6) | grp8;
                float a = dot128(Wskip0 + s*128, ru, ln8);
                if (ln8 == 0) s_skip[s] = a;
            }
        }
        __syncthreads();

        // ---- layers ----
        #pragma unroll 1
        for (int l = 0; l < NL; ++l) {
            const int d   = c_dil[l];
            const int pos = t & (d - 1);
            float* slot = ring + c_roff[l] + pos*128;

            // build qr = (q0[k], res[k])   (read before this layer's push)
            for (int k = tid; k < 128; k += NT)
                s_qr[k] = make_float2((t >= d) ? slot[k] : 0.f, s_res[k]);
            __syncthreads();

            // z rows: 256 dots of width 256 (taps interleaved with q0/res) + condz
            {
                const float* condl = condz + (l*4 + e)*256;
                #pragma unroll
                for (int p = 0; p < 4; ++p) {
                    int r = (p << 6) | grp8;
                    const float4* w4 = (const float4*)(Wc + (l*256 + r)*256) + ln8;
                    ull acc = pk2(0.f, 0.f);
                    #pragma unroll
                    for (int i = 0; i < 8; ++i) {
                        float4 wv = __ldg(w4 + (i << 3));
                        int k0 = (ln8 + (i << 3)) << 1;          // q/r pairs k0, k0+1
                        acc = fma2(pk2(wv.x, wv.y), qru[k0],     acc);
                        acc = fma2(pk2(wv.z, wv.w), qru[k0 + 1], acc);
                    }
                    float a = unp_sum(acc);
                    a += __shfl_down_sync(0xffffffffu, a, 4);
                    a += __shfl_down_sync(0xffffffffu, a, 2);
                    a += __shfl_down_sync(0xffffffffu, a, 1);
                    if (ln8 == 0) s_z[r] = a + condl[r];
                }
            }
            __syncthreads();

            // gated activation: sigmoid(gate)*tanh(out)
            for (int j = tid; j < 128; j += NT)
                s_h[j] = tanhf(s_z[128 + j]) / (1.f + expf(-s_z[j]));
            __syncthreads();

            // res update + skip accumulate + ring push (old res)
            {
                #pragma unroll
                for (int p = 0; p < 4; ++p) {
                    int u = (p << 6) | grp8;            // 0..255
                    int r = u & 127;
                    bool isSkip = (u >> 7) != 0;
                    float a = 0.f;
                    if (isSkip) {
                        a = dot128(Wskip + (l*128 + r)*128, hu, ln8);
                        if (ln8 == 0) s_skip[r] += a;
                    } else {
                        if (l < 15) a = dot128(Wres + (l*128 + r)*128, hu, ln8);
                        if (ln8 == 0) {
                            float old = s_res[r];
                            slot[r] = old;              // push this layer's input
                            if (l < 15) s_res[r] = old + a + __ldg(bres + l*128 + r);
                        }
                    }
                }
            }
            __syncthreads();
        }

        // ---- tail ----
        for (int s = tid; s < 128; s += NT)
            s_rl[s] = fmaxf(s_skip[s] + s_bsk[s], 0.f);
        __syncthreads();

        #pragma unroll
        for (int p = 0; p < 2; ++p) {                 // fc + cond_top (bfc folded), relu
            int s = (p << 6) | grp8;
            float a = dot128(Wfc + s*128, rlu, ln8);
            if (ln8 == 0) s_s2[s] = fmaxf(a + s_ct[e*128 + s], 0.f);
        }
        __syncthreads();

        #pragma unroll
        for (int p = 0; p < 4; ++p) {                 // logits
            int cls = (p << 6) | grp8;
            float a = dot128(Wlog + cls*128, s2u, ln8);
            if (ln8 == 0) {
                float lv = a + __ldg(blog + cls);
                out[(b*256 + cls)*TST + t] = lv;
                s_z[cls] = lv;                        // reuse z as logit store
            }
        }
        __syncthreads();

        // argmax (first-occurrence tie-break == jnp.argmax)
        if (tid < 32) {
            ull best = 0;
            #pragma unroll
            for (int m = 0; m < 8; ++m) {
                int c = tid*8 + m;
                ull key = ((ull)fkey(s_z[c]) << 32) | (unsigned)(255 - c);
                if (key > best) best = key;
            }
            #pragma unroll
            for (int off = 16; off > 0; off >>= 1) {
                ull o = __shfl_down_sync(0xffffffffu, best, off);
                if (o > best) best = o;
            }
            if (tid == 0) {
                int cls = 255 - (int)(best & 0xffu);
                s_xv[1] = s_xv[0];
                s_xv[0] = (float)cls / 127.5f - 1.0f;
            }
        }
        __syncthreads();
    }
}

// ---------------- launch ----------------
extern "C" void kernel_launch(void* const* d_in, const int* in_sizes, int n_in,
                              void* d_out, int out_size) {
    const float* enc       = (const float*)d_in[0];
    const float* Wf        = (const float*)d_in[1];
    const float* bf        = (const float*)d_in[2];
    const float* Wc        = (const float*)d_in[3];
    const float* bc        = (const float*)d_in[4];
    const float* Wcond     = (const float*)d_in[5];
    const float* Wres      = (const float*)d_in[6];
    const float* bres      = (const float*)d_in[7];
    const float* Wskip_l   = (const float*)d_in[8];
    const float* bskip_l   = (const float*)d_in[9];
    const float* Wskip0    = (const float*)d_in[10];
    const float* bskip0    = (const float*)d_in[11];
    const float* Wcond_top = (const float*)d_in[12];
    const float* Wfc       = (const float*)d_in[13];
    const float* bfc       = (const float*)d_in[14];
    const float* Wlog      = (const float*)d_in[15];
    const float* blog      = (const float*)d_in[16];
    float* out = (float*)d_out;

    wnet4<<<4, NT>>>(enc, Wf, bf, Wc, bc, Wcond, Wres, bres,
                     Wskip_l, bskip_l, Wskip0, bskip0, Wcond_top,
                     Wfc, bfc, Wlog, blog, out);
}